// round 8
// baseline (speedup 1.0000x reference)
#include <cuda_runtime.h>
#include <math.h>

#define BDIM 512
#define TDIM 512
#define IN0  64
#define HDIM 128
#define G3   384   // 3*H  (gate order r, z, n)

typedef unsigned long long u64;

// ---------------------------------------------------------------------------
// f32x2 packed helpers (batch-packed lanes)
// ---------------------------------------------------------------------------
__device__ __forceinline__ u64 splat2(unsigned int v) {
    u64 r; asm("mov.b64 %0, {%1, %1};" : "=l"(r) : "r"(v)); return r;
}
__device__ __forceinline__ void fma2(u64& d, u64 a, u64 b) {
    asm("fma.rn.f32x2 %0, %1, %2, %0;" : "+l"(d) : "l"(a), "l"(b));
}
__device__ __forceinline__ float2 unpack2(u64 v) {
    unsigned int lo, hi;
    asm("mov.b64 {%0, %1}, %2;" : "=r"(lo), "=r"(hi) : "l"(v));
    float2 f; f.x = __uint_as_float(lo); f.y = __uint_as_float(hi); return f;
}
__device__ __forceinline__ float sigmoid_f(float x) {
    return __fdividef(1.f, 1.f + __expf(-x));
}
__device__ __forceinline__ float tanh_f(float x) {
    // 2*sigmoid(2x) - 1 : short MUFU chain, rel err ~1e-6
    return __fmaf_rn(2.f, __fdividef(1.f, 1.f + __expf(-2.f * x)), -1.f);
}

// ---------------------------------------------------------------------------
// Scratch
// ---------------------------------------------------------------------------
__device__ float g_gi   [(size_t)BDIM * TDIM * G3];
__device__ float g_h1   [(size_t)BDIM * TDIM * HDIM];
__device__ float g_hlast[(size_t)BDIM * HDIM];

// ---------------------------------------------------------------------------
// gi GEMM (v5 proven, untouched): out[M,384] = X[M,K] @ W[384,K]^T + bias.
// ---------------------------------------------------------------------------
template <int K>
__global__ __launch_bounds__(256)
void gi_gemm(const float* __restrict__ X,
             const float* __restrict__ W,
             const float* __restrict__ bias)
{
    constexpr int TM  = 64;
    constexpr int NC  = 96;
    constexpr int XP  = 66;
    constexpr int WP2 = 98;

    extern __shared__ float sm[];
    float* xs = sm;
    float* ws = sm + K * XP;

    const int tid = threadIdx.x;
    const int rowbase = blockIdx.x * TM;

    for (int idx = tid; idx < TM * K; idx += 256) {
        int r = idx / K, k = idx - r * K;
        xs[k * XP + r] = X[(size_t)(rowbase + r) * K + k];
    }

    const int rg = tid >> 4;
    const int gg = tid & 15;
    float* out = g_gi;

    for (int c = 0; c < 4; ++c) {
        __syncthreads();
        for (int idx = tid; idx < NC * K; idx += 256) {
            int g = idx / K, k = idx - g * K;
            ws[k * WP2 + g] = W[(size_t)(c * NC + g) * K + k];
        }
        __syncthreads();

        u64 acc[4][3];
        #pragma unroll
        for (int i = 0; i < 4; ++i)
            #pragma unroll
            for (int p = 0; p < 3; ++p) acc[i][p] = 0ull;

        const float* xp0 = &xs[rg * 4];
        const float* wp0 = &ws[gg * 6];

        #pragma unroll 4
        for (int k = 0; k < K; ++k) {
            u64 x0 = splat2(__float_as_uint(xp0[k * XP + 0]));
            u64 x1 = splat2(__float_as_uint(xp0[k * XP + 1]));
            u64 x2 = splat2(__float_as_uint(xp0[k * XP + 2]));
            u64 x3 = splat2(__float_as_uint(xp0[k * XP + 3]));
            const u64* wrow = (const u64*)&wp0[k * WP2];
            u64 w01 = wrow[0], w23 = wrow[1], w45 = wrow[2];
            fma2(acc[0][0], x0, w01); fma2(acc[0][1], x0, w23); fma2(acc[0][2], x0, w45);
            fma2(acc[1][0], x1, w01); fma2(acc[1][1], x1, w23); fma2(acc[1][2], x1, w45);
            fma2(acc[2][0], x2, w01); fma2(acc[2][1], x2, w23); fma2(acc[2][2], x2, w45);
            fma2(acc[3][0], x3, w01); fma2(acc[3][1], x3, w23); fma2(acc[3][2], x3, w45);
        }

        __syncthreads();

        const int g0 = c * NC + gg * 6;
        #pragma unroll
        for (int p = 0; p < 3; ++p) {
            float b0 = bias[g0 + 2 * p];
            float b1 = bias[g0 + 2 * p + 1];
            #pragma unroll
            for (int i = 0; i < 4; ++i) {
                float2 v = unpack2(acc[i][p]);
                int r = rg * 4 + i;
                ws[r * NC + gg * 6 + 2 * p]     = v.x + b0;
                ws[r * NC + gg * 6 + 2 * p + 1] = v.y + b1;
            }
        }
        __syncthreads();

        #pragma unroll
        for (int v = 0; v < (TM * NC / 4) / 256; ++v) {
            int idx = (v * 256 + tid) * 4;
            int r = idx / NC, col = idx - r * NC;
            float4 val = *(const float4*)&ws[idx];
            *(float4*)&out[(size_t)(rowbase + r) * G3 + c * NC + col] = val;
        }
    }
}

// ---------------------------------------------------------------------------
// Persistent GRU recurrence v8: 1024 threads (8 warps/SMSP).
// q = tid&7 (k-eighth, INTERLEAVED k = kk*8+q -> contiguous 128B h loads),
// j = tid>>3 (hidden unit). r/z weights in regs (32 uints), n via quad
// LDS.128. Eighths folded to quarters with one shfl_xor(4) round; gate
// tail identical to proven v5 (q<4 threads, smem reduction RP=13).
// ---------------------------------------------------------------------------
template <int WRITE_SEQ>
__global__ __launch_bounds__(1024, 1)
void gru_recurrent(const float* __restrict__ Whh,
                   const float* __restrict__ bhh)
{
    constexpr int RP = 13;

    extern __shared__ float sm[];
    float* Wn4 = sm;                     // [4 kkg][1024 tid][4 m] quad layout
    float* hs  = Wn4 + 4 * 1024 * 4;     // [128][4] h state, 16B-aligned
    float* red = hs + HDIM * 4;          // [4][128][RP]

    const int tid = threadIdx.x;
    const int q   = tid & 7;
    const int j   = tid >> 3;
    const int qq4 = q & 3;
    const int b0  = blockIdx.x * 4;

    // Stage n-gate weights in consuming-tid quad order (one-time).
    for (int idx = tid; idx < 4 * 1024 * 4; idx += 1024) {
        int kkg = idx >> 12;
        int rem = idx & 4095;
        int t2  = rem >> 2;
        int m   = rem & 3;
        int j2  = t2 >> 3, q2 = t2 & 7;
        int k2  = (kkg * 4 + m) * 8 + q2;
        Wn4[idx] = Whh[(size_t)(2 * HDIM + j2) * HDIM + k2];
    }
    if (tid < 512) hs[tid] = 0.f;
    __syncthreads();

    // r/z weights into registers (k = kk*8 + q, kk = 0..15).
    unsigned int wr[16], wz[16];
    #pragma unroll
    for (int kk = 0; kk < 16; ++kk) {
        int k = kk * 8 + q;
        wr[kk] = __float_as_uint(__ldg(Whh + (size_t)j * HDIM + k));
        wz[kk] = __float_as_uint(__ldg(Whh + (size_t)(HDIM + j) * HDIM + k));
    }
    const float bhr = bhh[j];
    const float bhz = bhh[HDIM + j];
    const float bhn = bhh[2 * HDIM + j];

    float* myred = &red[(qq4 * HDIM + j) * RP];
    const float* gi = g_gi + (size_t)(b0 + qq4) * TDIM * G3;
    const ulonglong2* h16 = (const ulonglong2*)hs;    // hs[k][0..3] = 16B
    const uint4* wn4p = (const uint4*)Wn4 + tid;      // stride 1024 per kkg

    for (int t = 0; t < TDIM; ++t) {
        // Prefetch input-side preactivations (covered by the matvec).
        const float* gip = gi + (size_t)t * G3;
        float ir  = gip[j];
        float iz  = gip[HDIM + j];
        float in_ = gip[2 * HDIM + j];

        u64 a_r01 = 0, a_r23 = 0, a_z01 = 0, a_z23 = 0, a_n01 = 0, a_n23 = 0;

        #pragma unroll
        for (int kkg = 0; kkg < 4; ++kkg) {
            uint4 wq = wn4p[kkg * 1024];               // wn for 4 kk, coalesced
            #pragma unroll
            for (int m = 0; m < 4; ++m) {
                int kk = kkg * 4 + m;
                ulonglong2 hv = h16[kk * 8 + q];       // 128B contiguous/warp
                u64 wr2 = splat2(wr[kk]);
                u64 wz2 = splat2(wz[kk]);
                unsigned int wnu = (m == 0) ? wq.x : (m == 1) ? wq.y
                                 : (m == 2) ? wq.z : wq.w;
                u64 wn2 = splat2(wnu);
                fma2(a_r01, wr2, hv.x); fma2(a_r23, wr2, hv.y);
                fma2(a_z01, wz2, hv.x); fma2(a_z23, wz2, hv.y);
                fma2(a_n01, wn2, hv.x); fma2(a_n23, wn2, hv.y);
            }
        }

        // Fold eighths q and q+4 into quarter qq4 (one intra-warp shfl round).
        float2 r01 = unpack2(a_r01), r23 = unpack2(a_r23);
        float2 z01 = unpack2(a_z01), z23 = unpack2(a_z23);
        float2 n01 = unpack2(a_n01), n23 = unpack2(a_n23);
        r01.x += __shfl_xor_sync(0xFFFFFFFFu, r01.x, 4);
        r01.y += __shfl_xor_sync(0xFFFFFFFFu, r01.y, 4);
        r23.x += __shfl_xor_sync(0xFFFFFFFFu, r23.x, 4);
        r23.y += __shfl_xor_sync(0xFFFFFFFFu, r23.y, 4);
        z01.x += __shfl_xor_sync(0xFFFFFFFFu, z01.x, 4);
        z01.y += __shfl_xor_sync(0xFFFFFFFFu, z01.y, 4);
        z23.x += __shfl_xor_sync(0xFFFFFFFFu, z23.x, 4);
        z23.y += __shfl_xor_sync(0xFFFFFFFFu, z23.y, 4);
        n01.x += __shfl_xor_sync(0xFFFFFFFFu, n01.x, 4);
        n01.y += __shfl_xor_sync(0xFFFFFFFFu, n01.y, 4);
        n23.x += __shfl_xor_sync(0xFFFFFFFFu, n23.x, 4);
        n23.y += __shfl_xor_sync(0xFFFFFFFFu, n23.y, 4);

        if (q < 4) {
            myred[0]  = r01.x; myred[1]  = r01.y;
            myred[2]  = r23.x; myred[3]  = r23.y;
            myred[4]  = z01.x; myred[5]  = z01.y;
            myred[6]  = z23.x; myred[7]  = z23.y;
            myred[8]  = n01.x; myred[9]  = n01.y;
            myred[10] = n23.x; myred[11] = n23.y;
        }
        __syncthreads();

        // Gate phase (v5-exact): thread (j, q<4) finishes batch b = q.
        if (q < 4) {
            const int b = q;
            float sr = 0.f, sz = 0.f, sn = 0.f;
            #pragma unroll
            for (int p = 0; p < 4; ++p) {
                const float* rp = &red[(p * HDIM + j) * RP];
                sr += rp[0 * 4 + b];
                sz += rp[1 * 4 + b];
                sn += rp[2 * 4 + b];
            }
            float r = sigmoid_f(ir + sr + bhr);
            float z = sigmoid_f(iz + sz + bhz);
            float n = tanh_f(in_ + r * (sn + bhn));
            float hold = hs[j * 4 + b];
            float hnew = n + z * (hold - n);
            hs[j * 4 + b] = hnew;
        }
        __syncthreads();

        // Coalesced sequence write (overlaps next step's matvec; hs is not
        // rewritten until after next step's first barrier).
        if (WRITE_SEQ) {
            if (tid < 512) {
                int b  = tid >> 7;
                int jj = tid & 127;
                g_h1[((size_t)(b0 + b) * TDIM + t) * HDIM + jj] = hs[jj * 4 + b];
            }
        } else if (t == TDIM - 1) {
            if (tid < 512) {
                int b  = tid >> 7;
                int jj = tid & 127;
                g_hlast[(size_t)(b0 + b) * HDIM + jj] = hs[jj * 4 + b];
            }
        }
    }
}

// ---------------------------------------------------------------------------
// Final FC (O = 1): one warp per batch.
// ---------------------------------------------------------------------------
__global__ void fc_kernel(const float* __restrict__ Wfc,
                          const float* __restrict__ bfc,
                          float* __restrict__ out)
{
    int w = (blockIdx.x * blockDim.x + threadIdx.x) >> 5;
    int lane = threadIdx.x & 31;
    if (w >= BDIM) return;
    const float* hp = g_hlast + (size_t)w * HDIM;
    float s = 0.f;
    #pragma unroll
    for (int k = lane; k < HDIM; k += 32) s += hp[k] * Wfc[k];
    #pragma unroll
    for (int o = 16; o; o >>= 1) s += __shfl_xor_sync(0xFFFFFFFFu, s, o);
    if (lane == 0) out[w] = s + bfc[0];
}

// ---------------------------------------------------------------------------
extern "C" void kernel_launch(void* const* d_in, const int* in_sizes, int n_in,
                              void* d_out, int out_size)
{
    const float* x     = (const float*)d_in[0];
    const float* W_ih0 = (const float*)d_in[1];
    const float* W_hh0 = (const float*)d_in[2];
    const float* b_ih0 = (const float*)d_in[3];
    const float* b_hh0 = (const float*)d_in[4];
    const float* W_ih1 = (const float*)d_in[5];
    const float* W_hh1 = (const float*)d_in[6];
    const float* b_ih1 = (const float*)d_in[7];
    const float* b_hh1 = (const float*)d_in[8];
    const float* W_fc  = (const float*)d_in[9];
    const float* b_fc  = (const float*)d_in[10];
    float* out = (float*)d_out;

    const int SMEM_G64  = (64  * 66 + 64  * 98) * 4;
    const int SMEM_G128 = (128 * 66 + 128 * 98) * 4;
    const int SMEM_REC  = (4 * 1024 * 4 + HDIM * 4 + 4 * HDIM * 13) * 4;  // 94,720 B

    cudaFuncSetAttribute(gi_gemm<64>,  cudaFuncAttributeMaxDynamicSharedMemorySize, SMEM_G64);
    cudaFuncSetAttribute(gi_gemm<128>, cudaFuncAttributeMaxDynamicSharedMemorySize, SMEM_G128);
    cudaFuncSetAttribute(gru_recurrent<1>, cudaFuncAttributeMaxDynamicSharedMemorySize, SMEM_REC);
    cudaFuncSetAttribute(gru_recurrent<0>, cudaFuncAttributeMaxDynamicSharedMemorySize, SMEM_REC);

    void* h1ptr = nullptr;
    cudaGetSymbolAddress(&h1ptr, g_h1);

    const int M = BDIM * TDIM;
    const int GEMM_GRID = M / 64;

    gi_gemm<64><<<GEMM_GRID, 256, SMEM_G64>>>(x, W_ih0, b_ih0);
    gru_recurrent<1><<<BDIM / 4, 1024, SMEM_REC>>>(W_hh0, b_hh0);
    gi_gemm<128><<<GEMM_GRID, 256, SMEM_G128>>>((const float*)h1ptr, W_ih1, b_ih1);
    gru_recurrent<0><<<BDIM / 4, 1024, SMEM_REC>>>(W_hh1, b_hh1);
    fc_kernel<<<BDIM / 4, 128>>>(W_fc, b_fc, out);
}

// round 9
// speedup vs baseline: 1.7540x; 1.7540x over previous
#include <cuda_runtime.h>
#include <math.h>

#define BDIM 512
#define TDIM 512
#define IN0  64
#define HDIM 128
#define G3   384   // 3*H  (gate order r, z, n)

typedef unsigned long long u64;

// ---------------------------------------------------------------------------
// f32x2 packed helpers (batch-packed lanes, v5 proven scheme)
// ---------------------------------------------------------------------------
__device__ __forceinline__ u64 splat2(unsigned int v) {
    u64 r; asm("mov.b64 %0, {%1, %1};" : "=l"(r) : "r"(v)); return r;
}
__device__ __forceinline__ void fma2(u64& d, u64 a, u64 b) {
    asm("fma.rn.f32x2 %0, %1, %2, %0;" : "+l"(d) : "l"(a), "l"(b));
}
__device__ __forceinline__ float2 unpack2(u64 v) {
    unsigned int lo, hi;
    asm("mov.b64 {%0, %1}, %2;" : "=r"(lo), "=r"(hi) : "l"(v));
    float2 f; f.x = __uint_as_float(lo); f.y = __uint_as_float(hi); return f;
}
__device__ __forceinline__ float sigmoid_f(float x) {
    return __fdividef(1.f, 1.f + __expf(-x));
}
__device__ __forceinline__ float tanh_f(float x) {
    // 2*sigmoid(2x) - 1 : short MUFU chain, rel err ~1e-6 (validated v6/v8)
    return __fmaf_rn(2.f, __fdividef(1.f, 1.f + __expf(-2.f * x)), -1.f);
}

// ---------------------------------------------------------------------------
// Scratch
// ---------------------------------------------------------------------------
__device__ float g_gi [(size_t)BDIM * TDIM * G3];
__device__ float g_h1 [(size_t)BDIM * TDIM * HDIM];
__device__ float g_hlast[(size_t)BDIM * HDIM];
__device__ float g_WT0[64  * G3];    // W_ih0 transposed: [K][384]
__device__ float g_WT1[128 * G3];    // W_ih1 transposed: [K][384]

// ---------------------------------------------------------------------------
// One-time W_ih transpose: WT[k][g] = W[g][k].  (few µs, per launch)
// ---------------------------------------------------------------------------
template <int K>
__global__ void transpose_w(const float* __restrict__ W, float* __restrict__ WT)
{
    int idx = blockIdx.x * blockDim.x + threadIdx.x;   // g*K + k, coalesced read
    if (idx >= G3 * K) return;
    int g = idx / K, k = idx - g * K;
    WT[k * G3 + g] = W[idx];
}

// ---------------------------------------------------------------------------
// gi GEMM v9: compute loop identical to v5; staging fully vectorized.
// xs row-major [r][K+4] (float4<->float4, conflict-free); ws [k][100] copied
// from pre-transposed WT with LDG.128/STS.128. Output staged + STG.128 flush.
// ---------------------------------------------------------------------------
template <int K>
__global__ __launch_bounds__(256)
void gi_gemm(const float* __restrict__ X,
             const float* __restrict__ WT,   // [K][384] transposed
             const float* __restrict__ bias)
{
    constexpr int TM  = 64;
    constexpr int NC  = 96;
    constexpr int XP  = K + 4;    // %4 == 0 -> float4 rows
    constexpr int WP2 = 100;      // [k][gate] pitch, %4 == 0

    extern __shared__ float sm[];
    float* xs = sm;               // [TM][XP] row-major
    float* ws = sm + TM * XP;     // [K][WP2]; reused as [64][96] staging

    const int tid = threadIdx.x;
    const int rowbase = blockIdx.x * TM;

    // Stage X row-major: float4 in, float4 out, conflict-free.
    for (int idx = tid; idx < TM * (K / 4); idx += 256) {
        int r = idx / (K / 4), kb = idx - r * (K / 4);
        float4 v = *(const float4*)&X[(size_t)(rowbase + r) * K + kb * 4];
        *(float4*)&xs[r * XP + kb * 4] = v;
    }

    const int rg = tid >> 4;      // 0..15 : row group (4 rows)
    const int gg = tid & 15;      // 0..15 : gate group (6 gates)
    float* out = g_gi;

    for (int c = 0; c < 4; ++c) {
        __syncthreads();
        // Stage W chunk from transposed global: coalesced float4 copy.
        for (int idx = tid; idx < K * (NC / 4); idx += 256) {
            int k = idx / (NC / 4), g4 = idx - k * (NC / 4);
            float4 v = *(const float4*)&WT[(size_t)k * G3 + c * NC + g4 * 4];
            *(float4*)&ws[k * WP2 + g4 * 4] = v;
        }
        __syncthreads();

        u64 acc[4][3];
        #pragma unroll
        for (int i = 0; i < 4; ++i)
            #pragma unroll
            for (int p = 0; p < 3; ++p) acc[i][p] = 0ull;

        const float* xr0 = &xs[(rg * 4 + 0) * XP];
        const float* xr1 = &xs[(rg * 4 + 1) * XP];
        const float* xr2 = &xs[(rg * 4 + 2) * XP];
        const float* xr3 = &xs[(rg * 4 + 3) * XP];
        const float* wp0 = &ws[gg * 6];

        #pragma unroll 4
        for (int k = 0; k < K; ++k) {
            u64 x0 = splat2(__float_as_uint(xr0[k]));   // warp-broadcast LDS
            u64 x1 = splat2(__float_as_uint(xr1[k]));
            u64 x2 = splat2(__float_as_uint(xr2[k]));
            u64 x3 = splat2(__float_as_uint(xr3[k]));
            const u64* wrow = (const u64*)&wp0[k * WP2];  // 3x LDS.64
            u64 w01 = wrow[0], w23 = wrow[1], w45 = wrow[2];
            fma2(acc[0][0], x0, w01); fma2(acc[0][1], x0, w23); fma2(acc[0][2], x0, w45);
            fma2(acc[1][0], x1, w01); fma2(acc[1][1], x1, w23); fma2(acc[1][2], x1, w45);
            fma2(acc[2][0], x2, w01); fma2(acc[2][1], x2, w23); fma2(acc[2][2], x2, w45);
            fma2(acc[3][0], x3, w01); fma2(acc[3][1], x3, w23); fma2(acc[3][2], x3, w45);
        }

        __syncthreads();  // done reading weights; reuse ws as staging

        const int g0 = c * NC + gg * 6;
        #pragma unroll
        for (int p = 0; p < 3; ++p) {
            float b0 = bias[g0 + 2 * p];
            float b1 = bias[g0 + 2 * p + 1];
            #pragma unroll
            for (int i = 0; i < 4; ++i) {
                float2 v = unpack2(acc[i][p]);
                int r = rg * 4 + i;
                ws[r * NC + gg * 6 + 2 * p]     = v.x + b0;
                ws[r * NC + gg * 6 + 2 * p + 1] = v.y + b1;
            }
        }
        __syncthreads();

        #pragma unroll
        for (int v = 0; v < (TM * NC / 4) / 256; ++v) {
            int idx = (v * 256 + tid) * 4;
            int r = idx / NC, col = idx - r * NC;
            float4 val = *(const float4*)&ws[idx];
            *(float4*)&out[(size_t)(rowbase + r) * G3 + c * NC + col] = val;
        }
    }
}

// ---------------------------------------------------------------------------
// Persistent GRU recurrence (v5 exact + MUFU tanh, dead bh[] removed).
// 512 thr: j = tid&127 (hidden unit), q = tid>>7 (k-quarter, inter-warp).
// r/z weights in regs; n weights quad-LDS.128; h as LDS.128 broadcast per k.
// smem reduction (RP=13), 2 barriers/step.
// ---------------------------------------------------------------------------
template <int WRITE_SEQ>
__global__ __launch_bounds__(512, 1)
void gru_recurrent(const float* __restrict__ Whh,
                   const float* __restrict__ bhh)
{
    constexpr int RP = 13;

    extern __shared__ float sm[];
    float* Wn4 = sm;                     // [8][512][4] quad layout
    float* hs  = Wn4 + 8 * 512 * 4;      // [128][4], 16B-aligned
    float* red = hs + HDIM * 4;          // [4][128][RP]

    const int tid = threadIdx.x;
    const int j   = tid & 127;
    const int q   = tid >> 7;
    const int b0  = blockIdx.x * 4;
    const int k0  = q * 32;

    // Stage n-gate weights in consuming-tid quad order (one-time).
    for (int idx = tid; idx < 8 * 512 * 4; idx += 512) {
        int kkg = idx >> 11;
        int rem = idx & 2047;
        int t2  = rem >> 2;
        int m   = rem & 3;
        int j2  = t2 & 127, q2 = t2 >> 7;
        int k2  = q2 * 32 + kkg * 4 + m;
        Wn4[idx] = Whh[(size_t)(2 * HDIM + j2) * HDIM + k2];
    }
    hs[tid & 511] = 0.f;

    // r/z weights into registers (k = k0 + kk).
    unsigned int wrz[64];
    #pragma unroll
    for (int kk = 0; kk < 32; ++kk) {
        wrz[2 * kk]     = __float_as_uint(__ldg(Whh + (size_t)j * HDIM + k0 + kk));
        wrz[2 * kk + 1] = __float_as_uint(__ldg(Whh + (size_t)(HDIM + j) * HDIM + k0 + kk));
    }
    const float bhr = bhh[j];
    const float bhz = bhh[HDIM + j];
    const float bhn = bhh[2 * HDIM + j];

    __syncthreads();

    float* myred = &red[(q * HDIM + j) * RP];
    const float* gi = g_gi + (size_t)(b0 + q) * TDIM * G3;
    const ulonglong2* h16 = (const ulonglong2*)hs;     // one 16B broadcast per k
    const uint4* wn4p = (const uint4*)Wn4 + tid;       // stride 512 uint4 per kkg

    for (int t = 0; t < TDIM; ++t) {
        // Prefetch input-side preactivations (covered by the matvec).
        const float* gip = gi + (size_t)t * G3;
        float ir  = gip[j];
        float iz  = gip[HDIM + j];
        float in_ = gip[2 * HDIM + j];

        u64 a_r01 = 0, a_r23 = 0, a_z01 = 0, a_z23 = 0, a_n01 = 0, a_n23 = 0;

        #pragma unroll
        for (int kkg = 0; kkg < 8; ++kkg) {
            uint4 wq = wn4p[kkg * 512];                 // wn for 4 k, coalesced
            #pragma unroll
            for (int m = 0; m < 4; ++m) {
                int kk = kkg * 4 + m;
                ulonglong2 hv = h16[k0 + kk];           // LDS.128 broadcast
                u64 wr2 = splat2(wrz[2 * kk]);
                u64 wz2 = splat2(wrz[2 * kk + 1]);
                unsigned int wnu = (m == 0) ? wq.x : (m == 1) ? wq.y
                                 : (m == 2) ? wq.z : wq.w;
                u64 wn2 = splat2(wnu);
                fma2(a_r01, wr2, hv.x); fma2(a_r23, wr2, hv.y);
                fma2(a_z01, wz2, hv.x); fma2(a_z23, wz2, hv.y);
                fma2(a_n01, wn2, hv.x); fma2(a_n23, wn2, hv.y);
            }
        }

        {
            float2 v;
            v = unpack2(a_r01); myred[0]  = v.x; myred[1]  = v.y;
            v = unpack2(a_r23); myred[2]  = v.x; myred[3]  = v.y;
            v = unpack2(a_z01); myred[4]  = v.x; myred[5]  = v.y;
            v = unpack2(a_z23); myred[6]  = v.x; myred[7]  = v.y;
            v = unpack2(a_n01); myred[8]  = v.x; myred[9]  = v.y;
            v = unpack2(a_n23); myred[10] = v.x; myred[11] = v.y;
        }
        __syncthreads();

        // Gate phase: thread (j, q) finishes batch b = q.
        const int b = q;
        float sr = 0.f, sz = 0.f, sn = 0.f;
        #pragma unroll
        for (int qq = 0; qq < 4; ++qq) {
            const float* rp = &red[(qq * HDIM + j) * RP];
            sr += rp[0 * 4 + b];
            sz += rp[1 * 4 + b];
            sn += rp[2 * 4 + b];
        }
        float r = sigmoid_f(ir + sr + bhr);
        float z = sigmoid_f(iz + sz + bhz);
        float n = tanh_f(in_ + r * (sn + bhn));
        float hold = hs[j * 4 + b];
        float hnew = n + z * (hold - n);

        hs[j * 4 + b] = hnew;
        if (WRITE_SEQ) {
            g_h1[((size_t)(b0 + b) * TDIM + t) * HDIM + j] = hnew;  // coalesced
        } else if (t == TDIM - 1) {
            g_hlast[(size_t)(b0 + b) * HDIM + j] = hnew;
        }
        __syncthreads();
    }
}

// ---------------------------------------------------------------------------
// Final FC (O = 1): one warp per batch.
// ---------------------------------------------------------------------------
__global__ void fc_kernel(const float* __restrict__ Wfc,
                          const float* __restrict__ bfc,
                          float* __restrict__ out)
{
    int w = (blockIdx.x * blockDim.x + threadIdx.x) >> 5;
    int lane = threadIdx.x & 31;
    if (w >= BDIM) return;
    const float* hp = g_hlast + (size_t)w * HDIM;
    float s = 0.f;
    #pragma unroll
    for (int k = lane; k < HDIM; k += 32) s += hp[k] * Wfc[k];
    #pragma unroll
    for (int o = 16; o; o >>= 1) s += __shfl_xor_sync(0xFFFFFFFFu, s, o);
    if (lane == 0) out[w] = s + bfc[0];
}

// ---------------------------------------------------------------------------
extern "C" void kernel_launch(void* const* d_in, const int* in_sizes, int n_in,
                              void* d_out, int out_size)
{
    const float* x     = (const float*)d_in[0];
    const float* W_ih0 = (const float*)d_in[1];
    const float* W_hh0 = (const float*)d_in[2];
    const float* b_ih0 = (const float*)d_in[3];
    const float* b_hh0 = (const float*)d_in[4];
    const float* W_ih1 = (const float*)d_in[5];
    const float* W_hh1 = (const float*)d_in[6];
    const float* b_ih1 = (const float*)d_in[7];
    const float* b_hh1 = (const float*)d_in[8];
    const float* W_fc  = (const float*)d_in[9];
    const float* b_fc  = (const float*)d_in[10];
    float* out = (float*)d_out;

    const int SMEM_G64  = (64 * 68  + 64  * 100) * 4;   // 43,008 B
    const int SMEM_G128 = (64 * 132 + 128 * 100) * 4;   // 85,504 B
    const int SMEM_REC  = (8 * 512 * 4 + HDIM * 4 + 4 * HDIM * 13) * 4; // 94,208 B

    cudaFuncSetAttribute(gi_gemm<64>,  cudaFuncAttributeMaxDynamicSharedMemorySize, SMEM_G64);
    cudaFuncSetAttribute(gi_gemm<128>, cudaFuncAttributeMaxDynamicSharedMemorySize, SMEM_G128);
    cudaFuncSetAttribute(gru_recurrent<1>, cudaFuncAttributeMaxDynamicSharedMemorySize, SMEM_REC);
    cudaFuncSetAttribute(gru_recurrent<0>, cudaFuncAttributeMaxDynamicSharedMemorySize, SMEM_REC);

    void* h1ptr = nullptr;
    cudaGetSymbolAddress(&h1ptr, g_h1);
    void* wt0ptr = nullptr;
    cudaGetSymbolAddress(&wt0ptr, g_WT0);
    void* wt1ptr = nullptr;
    cudaGetSymbolAddress(&wt1ptr, g_WT1);

    const int M = BDIM * TDIM;
    const int GEMM_GRID = M / 64;

    transpose_w<64> <<<(G3 * 64  + 255) / 256, 256>>>(W_ih0, (float*)wt0ptr);
    transpose_w<128><<<(G3 * 128 + 255) / 256, 256>>>(W_ih1, (float*)wt1ptr);

    gi_gemm<64><<<GEMM_GRID, 256, SMEM_G64>>>(x, (const float*)wt0ptr, b_ih0);
    gru_recurrent<1><<<BDIM / 4, 512, SMEM_REC>>>(W_hh0, b_hh0);
    gi_gemm<128><<<GEMM_GRID, 256, SMEM_G128>>>((const float*)h1ptr, (const float*)wt1ptr, b_ih1);
    gru_recurrent<0><<<BDIM / 4, 512, SMEM_REC>>>(W_hh1, b_hh1);
    fc_kernel<<<BDIM / 4, 128>>>(W_fc, b_fc, out);
}